// round 2
// baseline (speedup 1.0000x reference)
#include <cuda_runtime.h>
#include <cuda_bf16.h>
#include <math.h>

#define T 8192
#define C 512
#define IDIM 64
#define E 32
#define NEGF (-3.3895313892515355e+38f)

// routing-weight scratch (allocation-free rule: __device__ global)
__device__ float g_rw[(size_t)T * E];

// ---------------------------------------------------------------------------
// Kernel 1: gating. 256 threads = 8 warps, one warp per token, lane = expert.
// ---------------------------------------------------------------------------
__global__ void gate_kernel(const float* __restrict__ x,
                            const float* __restrict__ sim,
                            const float* __restrict__ gates,
                            float* __restrict__ out_pre,
                            float* __restrict__ out_mask)
{
    const int warp = threadIdx.x >> 5;
    const int lane = threadIdx.x & 31;
    const int t = blockIdx.x * 8 + warp;

    __shared__ float xs[8][C];

    // load row + sum of squares
    const float* xr = x + (size_t)t * C;
    float ss = 0.f;
#pragma unroll
    for (int k = 0; k < C / 32; k++) {
        float v = xr[lane + k * 32];
        xs[warp][lane + k * 32] = v;
        ss += v * v;
    }
#pragma unroll
    for (int o = 16; o; o >>= 1) ss += __shfl_xor_sync(0xffffffffu, ss, o);
    const float invx = 1.0f / fmaxf(sqrtf(ss), 1e-12f);
    __syncwarp();

    // lane e: dot with sim column e + column sumsq (fused norm)
    const int e = lane;
    float dot = 0.f, cs = 0.f;
#pragma unroll 8
    for (int c = 0; c < C; c++) {
        float s = sim[c * E + e];
        dot = fmaf(xs[warp][c], s, dot);
        cs = fmaf(s, s, cs);
    }
    const float logit = dot * invx * (1.0f / fmaxf(sqrtf(cs), 1e-12f));

    const float pre   = logit - 1.0f / (1.0f + expf(-gates[e]));
    const float gated = fmaxf(pre, 0.0f);

    const unsigned act = __ballot_sync(0xffffffffu, gated > 0.0f);

    float m;
    if (act == 0u) {
        // token inactive -> top-16 fallback (jax top_k tie-break: lower index wins)
        int rank = 0;
#pragma unroll
        for (int j = 0; j < 32; j++) {
            float lj = __shfl_sync(0xffffffffu, logit, j);
            rank += (lj > logit) || (lj == logit && j < e);
        }
        m = (rank < (E / 2)) ? 1.0f : 0.0f;
    } else {
        m = (gated > 0.0f) ? 1.0f : 0.0f;
    }

    const float masked = (m > 0.0f) ? gated : NEGF;
    float mx = masked;
#pragma unroll
    for (int o = 16; o; o >>= 1) mx = fmaxf(mx, __shfl_xor_sync(0xffffffffu, mx, o));
    float ex = expf(masked - mx);
    float sum = ex;
#pragma unroll
    for (int o = 16; o; o >>= 1) sum += __shfl_xor_sync(0xffffffffu, sum, o);
    const float w = ex / sum;

    out_pre[(size_t)t * E + e]  = pre;
    out_mask[(size_t)t * E + e] = m;
    g_rw[(size_t)t * E + e]     = w;
}

// ---------------------------------------------------------------------------
// Kernel 2: dense experts. Block = (64-token tile, 1 expert), 256 threads.
// GEMM1 (64x64, K=512) -> exact GELU -> GEMM2 (64x512, K=64) -> feo *= mask.
// Shared memory is a 48 KB union:
//   phase A: [0:16K) Xs(64x64)  [16K:32K) W1s(64x64)
//   phase B: [0:16K) Hs(64x64)  [16K:48K) W2s(64x128)
// ---------------------------------------------------------------------------
__global__ __launch_bounds__(256) void expert_kernel(
    const float* __restrict__ x,
    const float* __restrict__ W1,
    const float* __restrict__ W2,
    const float* __restrict__ mask,
    float* __restrict__ feo)
{
    __shared__ float smem[12288];   // 48 KB
    __shared__ float msk[64];

    const int e   = blockIdx.y;
    const int t0  = blockIdx.x * 64;
    const int tid = threadIdx.x;

    if (tid < 64) msk[tid] = mask[(size_t)(t0 + tid) * E + e];

    float* Xs  = smem;          // [64][64]
    float* W1s = smem + 4096;   // [64][64]

    // GEMM1: per-thread 4 rows x 4 i.  rg = tid/16 -> rows, ig = tid%16 -> i.
    const int rg = tid >> 4;
    const int ig = tid & 15;
    float acc[4][4] = {};

    const float* W1e = W1 + (size_t)e * C * IDIM;

    for (int kk = 0; kk < C; kk += 64) {
#pragma unroll
        for (int i = tid; i < 4096; i += 256) {
            int r = i >> 6, c = i & 63;
            Xs[i] = x[(size_t)(t0 + r) * C + kk + c];
        }
#pragma unroll
        for (int i = tid; i < 4096; i += 256)
            W1s[i] = W1e[(size_t)kk * IDIM + i];
        __syncthreads();

#pragma unroll 4
        for (int k = 0; k < 64; k++) {
            float xv[4];
#pragma unroll
            for (int j = 0; j < 4; j++) xv[j] = Xs[(rg * 4 + j) * 64 + k];
            float4 wv = *(const float4*)&W1s[k * 64 + ig * 4];
#pragma unroll
            for (int j = 0; j < 4; j++) {
                acc[j][0] = fmaf(xv[j], wv.x, acc[j][0]);
                acc[j][1] = fmaf(xv[j], wv.y, acc[j][1]);
                acc[j][2] = fmaf(xv[j], wv.z, acc[j][2]);
                acc[j][3] = fmaf(xv[j], wv.w, acc[j][3]);
            }
        }
        __syncthreads();
    }

    // GELU (exact erf) -> Hs (reuses Xs region; safe after trailing sync)
    float* Hs = smem;
#pragma unroll
    for (int j = 0; j < 4; j++)
#pragma unroll
        for (int i2 = 0; i2 < 4; i2++) {
            float h = acc[j][i2];
            h = 0.5f * h * (1.0f + erff(h * 0.70710678118654752f));
            Hs[(rg * 4 + j) * 64 + ig * 4 + i2] = h;
        }
    __syncthreads();

    // GEMM2: Y[64][512] in c-chunks of 128. Warp w -> rows {w, w+8, ..., w+56},
    // lane -> float4 at c_local = lane*4 (coalesced 512 B stores per row).
    float* W2s = smem + 4096;   // [64][128]
    const float* W2e = W2 + (size_t)e * IDIM * C;
    const int w    = tid >> 5;
    const int lane = tid & 31;

    for (int cc = 0; cc < C; cc += 128) {
#pragma unroll
        for (int i = tid; i < 8192; i += 256) {
            int k = i >> 7, c = i & 127;
            W2s[i] = W2e[(size_t)k * C + cc + c];
        }
        __syncthreads();

        float y[8][4] = {};
#pragma unroll 4
        for (int k = 0; k < 64; k++) {
            float4 wv = *(const float4*)&W2s[k * 128 + lane * 4];
#pragma unroll
            for (int rr = 0; rr < 8; rr++) {
                float h = Hs[(w + rr * 8) * 64 + k];
                y[rr][0] = fmaf(h, wv.x, y[rr][0]);
                y[rr][1] = fmaf(h, wv.y, y[rr][1]);
                y[rr][2] = fmaf(h, wv.z, y[rr][2]);
                y[rr][3] = fmaf(h, wv.w, y[rr][3]);
            }
        }

#pragma unroll
        for (int rr = 0; rr < 8; rr++) {
            int r = w + rr * 8;
            float m = msk[r];
            float4 o = make_float4(y[rr][0] * m, y[rr][1] * m,
                                   y[rr][2] * m, y[rr][3] * m);
            *(float4*)&feo[((size_t)(t0 + r) * E + e) * C + cc + lane * 4] = o;
        }
        __syncthreads();
    }
}

// ---------------------------------------------------------------------------
// Kernel 3: combine. One token per block, 128 threads, float4 loads,
// skip experts with exactly-zero routing weight (softmax of NEG underflows
// to 0, so the skip is exact).
// ---------------------------------------------------------------------------
__global__ void combine_kernel(const float* __restrict__ feo,
                               float* __restrict__ out)
{
    const int t   = blockIdx.x;
    const int tid = threadIdx.x;
    __shared__ float w[E];
    if (tid < E) w[tid] = g_rw[(size_t)t * E + tid];
    __syncthreads();

    float4 acc = make_float4(0.f, 0.f, 0.f, 0.f);
    const float4* base = (const float4*)(feo + (size_t)t * E * C);
    for (int e = 0; e < E; e++) {
        float we = w[e];
        if (we != 0.0f) {          // uniform branch (smem value)
            float4 v = base[e * (C / 4) + tid];
            acc.x = fmaf(we, v.x, acc.x);
            acc.y = fmaf(we, v.y, acc.y);
            acc.z = fmaf(we, v.z, acc.z);
            acc.w = fmaf(we, v.w, acc.w);
        }
    }
    ((float4*)(out + (size_t)t * C))[tid] = acc;
}

// ---------------------------------------------------------------------------
extern "C" void kernel_launch(void* const* d_in, const int* in_sizes, int n_in,
                              void* d_out, int out_size)
{
    const float* x     = (const float*)d_in[0];
    const float* sim   = (const float*)d_in[1];
    const float* gates = (const float*)d_in[2];
    const float* W1    = (const float*)d_in[3];
    const float* W2    = (const float*)d_in[4];

    float* out       = (float*)d_out;
    float* out_final = out;                                // (T, C)
    float* out_feo   = out_final + (size_t)T * C;          // (T, E, C)
    float* out_pre   = out_feo + (size_t)T * E * C;        // (T, E)
    float* out_mask  = out_pre + (size_t)T * E;            // (T, E)

    gate_kernel<<<T / 8, 256>>>(x, sim, gates, out_pre, out_mask);

    dim3 g2(T / 64, E);
    expert_kernel<<<g2, 256>>>(x, W1, W2, out_mask, out_feo);

    combine_kernel<<<T, 128>>>(out_feo, out_final);
}

// round 4
// speedup vs baseline: 1.0872x; 1.0872x over previous
#include <cuda_runtime.h>
#include <cuda_bf16.h>
#include <math.h>

#define T 8192
#define C 512
#define IDIM 64
#define E 32
#define NEGF (-3.3895313892515355e+38f)

// routing-weight scratch (allocation-free rule: __device__ global)
__device__ float g_rw[(size_t)T * E];

// ---- packed fp32x2 helpers (sm_100+; ptxas never emits these from C++) ----
__device__ __forceinline__ unsigned long long pack2(float lo, float hi) {
    unsigned long long r;
    asm("mov.b64 %0, {%1, %2};" : "=l"(r) : "f"(lo), "f"(hi));
    return r;
}
__device__ __forceinline__ void unpack2(unsigned long long v, float& lo, float& hi) {
    asm("mov.b64 {%0, %1}, %2;" : "=f"(lo), "=f"(hi) : "l"(v));
}
__device__ __forceinline__ void ffma2(unsigned long long& d,
                                      unsigned long long a,
                                      unsigned long long b) {
    asm("fma.rn.f32x2 %0, %1, %2, %0;" : "+l"(d) : "l"(a), "l"(b));
}

// ---------------------------------------------------------------------------
// Kernel 1: gating. 256 threads = 8 warps, one warp per token, lane = expert.
// ---------------------------------------------------------------------------
__global__ void gate_kernel(const float* __restrict__ x,
                            const float* __restrict__ sim,
                            const float* __restrict__ gates,
                            float* __restrict__ out_pre,
                            float* __restrict__ out_mask)
{
    const int warp = threadIdx.x >> 5;
    const int lane = threadIdx.x & 31;
    const int t = blockIdx.x * 8 + warp;

    __shared__ float xs[8][C];

    const float* xr = x + (size_t)t * C;
    float ss = 0.f;
#pragma unroll
    for (int k = 0; k < C / 32; k++) {
        float v = xr[lane + k * 32];
        xs[warp][lane + k * 32] = v;
        ss += v * v;
    }
#pragma unroll
    for (int o = 16; o; o >>= 1) ss += __shfl_xor_sync(0xffffffffu, ss, o);
    const float invx = 1.0f / fmaxf(sqrtf(ss), 1e-12f);
    __syncwarp();

    const int e = lane;
    float dot = 0.f, cs = 0.f;
#pragma unroll 8
    for (int c = 0; c < C; c++) {
        float s = sim[c * E + e];
        dot = fmaf(xs[warp][c], s, dot);
        cs = fmaf(s, s, cs);
    }
    const float logit = dot * invx * (1.0f / fmaxf(sqrtf(cs), 1e-12f));

    const float pre   = logit - 1.0f / (1.0f + expf(-gates[e]));
    const float gated = fmaxf(pre, 0.0f);

    const unsigned act = __ballot_sync(0xffffffffu, gated > 0.0f);

    float m;
    if (act == 0u) {
        int rank = 0;
#pragma unroll
        for (int j = 0; j < 32; j++) {
            float lj = __shfl_sync(0xffffffffu, logit, j);
            rank += (lj > logit) || (lj == logit && j < e);
        }
        m = (rank < (E / 2)) ? 1.0f : 0.0f;
    } else {
        m = (gated > 0.0f) ? 1.0f : 0.0f;
    }

    const float masked = (m > 0.0f) ? gated : NEGF;
    float mx = masked;
#pragma unroll
    for (int o = 16; o; o >>= 1) mx = fmaxf(mx, __shfl_xor_sync(0xffffffffu, mx, o));
    float ex = expf(masked - mx);
    float sum = ex;
#pragma unroll
    for (int o = 16; o; o >>= 1) sum += __shfl_xor_sync(0xffffffffu, sum, o);
    const float w = ex / sum;

    out_pre[(size_t)t * E + e]  = pre;
    out_mask[(size_t)t * E + e] = m;
    g_rw[(size_t)t * E + e]     = w;
}

// ---------------------------------------------------------------------------
// Kernel 2: dense experts, packed-f32x2 FMA version.
// Block = (64-token tile, 1 expert), 256 threads.
// ---------------------------------------------------------------------------
__global__ __launch_bounds__(256) void expert_kernel(
    const float* __restrict__ x,
    const float* __restrict__ W1,
    const float* __restrict__ W2,
    const float* __restrict__ mask,
    float* __restrict__ feo)
{
    __shared__ float smem[12288];   // 48 KB
    __shared__ float msk[64];

    const int e   = blockIdx.y;
    const int t0  = blockIdx.x * 64;
    const int tid = threadIdx.x;

    if (tid < 64) msk[tid] = mask[(size_t)(t0 + tid) * E + e];

    float* Xs  = smem;          // [64][64]
    float* W1s = smem + 4096;   // [64][64]

    // GEMM1: per-thread 4 rows x 4 i, accumulators paired over i.
    const int rg = tid >> 4;
    const int ig = tid & 15;
    unsigned long long accp[4][2] = {};

    const float* W1e = W1 + (size_t)e * C * IDIM;

    for (int kk = 0; kk < C; kk += 64) {
#pragma unroll
        for (int i = tid; i < 4096; i += 256) {
            int r = i >> 6, c = i & 63;
            Xs[i] = x[(size_t)(t0 + r) * C + kk + c];
        }
#pragma unroll
        for (int i = tid; i < 4096; i += 256)
            W1s[i] = W1e[(size_t)kk * IDIM + i];
        __syncthreads();

#pragma unroll 4
        for (int k = 0; k < 64; k++) {
            float4 wv = *(const float4*)&W1s[k * 64 + ig * 4];
            unsigned long long wp0 = pack2(wv.x, wv.y);
            unsigned long long wp1 = pack2(wv.z, wv.w);
#pragma unroll
            for (int j = 0; j < 4; j++) {
                float xv = Xs[(rg * 4 + j) * 64 + k];
                unsigned long long xp = pack2(xv, xv);
                ffma2(accp[j][0], xp, wp0);
                ffma2(accp[j][1], xp, wp1);
            }
        }
        __syncthreads();
    }

    // GELU (exact erf) -> Hs
    float* Hs = smem;
#pragma unroll
    for (int j = 0; j < 4; j++) {
        float v[4];
        unpack2(accp[j][0], v[0], v[1]);
        unpack2(accp[j][1], v[2], v[3]);
#pragma unroll
        for (int i2 = 0; i2 < 4; i2++) {
            float h = v[i2];
            h = 0.5f * h * (1.0f + erff(h * 0.70710678118654752f));
            Hs[(rg * 4 + j) * 64 + ig * 4 + i2] = h;
        }
    }
    __syncthreads();

    // GEMM2: Y[64][512] in c-chunks of 128, accumulators paired over c.
    float* W2s = smem + 4096;   // [64][128]
    const float* W2e = W2 + (size_t)e * IDIM * C;
    const int w    = tid >> 5;
    const int lane = tid & 31;

    for (int cc = 0; cc < C; cc += 128) {
#pragma unroll
        for (int i = tid; i < 8192; i += 256) {
            int k = i >> 7, c = i & 127;
            W2s[i] = W2e[(size_t)k * C + cc + c];
        }
        __syncthreads();

        unsigned long long yp[8][2] = {};
#pragma unroll 4
        for (int k = 0; k < 64; k++) {
            float4 wv = *(const float4*)&W2s[k * 128 + lane * 4];
            unsigned long long wp0 = pack2(wv.x, wv.y);
            unsigned long long wp1 = pack2(wv.z, wv.w);
#pragma unroll
            for (int rr = 0; rr < 8; rr++) {
                float h = Hs[(w + rr * 8) * 64 + k];
                unsigned long long hp = pack2(h, h);
                ffma2(yp[rr][0], hp, wp0);
                ffma2(yp[rr][1], hp, wp1);
            }
        }

#pragma unroll
        for (int rr = 0; rr < 8; rr++) {
            int r = w + rr * 8;
            float m = msk[r];
            float4 o;
            unpack2(yp[rr][0], o.x, o.y);
            unpack2(yp[rr][1], o.z, o.w);
            o.x *= m; o.y *= m; o.z *= m; o.w *= m;
            *(float4*)&feo[((size_t)(t0 + r) * E + e) * C + cc + lane * 4] = o;
        }
        __syncthreads();
    }
}

// ---------------------------------------------------------------------------
// Kernel 3: combine. One token per block, 128 threads, float4 loads,
// skip experts with exactly-zero routing weight.
// ---------------------------------------------------------------------------
__global__ void combine_kernel(const float* __restrict__ feo,
                               float* __restrict__ out)
{
    const int t   = blockIdx.x;
    const int tid = threadIdx.x;
    __shared__ float w[E];
    if (tid < E) w[tid] = g_rw[(size_t)t * E + tid];
    __syncthreads();

    float4 acc = make_float4(0.f, 0.f, 0.f, 0.f);
    const float4* base = (const float4*)(feo + (size_t)t * E * C);
    for (int e = 0; e < E; e++) {
        float we = w[e];
        if (we != 0.0f) {
            float4 v = base[e * (C / 4) + tid];
            acc.x = fmaf(we, v.x, acc.x);
            acc.y = fmaf(we, v.y, acc.y);
            acc.z = fmaf(we, v.z, acc.z);
            acc.w = fmaf(we, v.w, acc.w);
        }
    }
    ((float4*)(out + (size_t)t * C))[tid] = acc;
}

// ---------------------------------------------------------------------------
extern "C" void kernel_launch(void* const* d_in, const int* in_sizes, int n_in,
                              void* d_out, int out_size)
{
    const float* x     = (const float*)d_in[0];
    const float* sim   = (const float*)d_in[1];
    const float* gates = (const float*)d_in[2];
    const float* W1    = (const float*)d_in[3];
    const float* W2    = (const float*)d_in[4];

    float* out       = (float*)d_out;
    float* out_final = out;                                // (T, C)
    float* out_feo   = out_final + (size_t)T * C;          // (T, E, C)
    float* out_pre   = out_feo + (size_t)T * E * C;        // (T, E)
    float* out_mask  = out_pre + (size_t)T * E;            // (T, E)

    gate_kernel<<<T / 8, 256>>>(x, sim, gates, out_pre, out_mask);

    dim3 g2(T / 64, E);
    expert_kernel<<<g2, 256>>>(x, W1, W2, out_mask, out_feo);

    combine_kernel<<<T, 128>>>(out_feo, out_final);
}